// round 3
// baseline (speedup 1.0000x reference)
#include <cuda_runtime.h>
#include <math.h>

#define NB 32
#define NH 512
#define NW 512
#define NM 96
#define NCo 263
#define SW 264
#define RANKSEL 105334u
#define CST 263

__constant__ float RL[16] = {
  0.05441584224308161f,   0.3128715909144659f,    0.6756307362980128f,
  0.5853546836548691f,   -0.015829105256023893f, -0.2840155429624281f,
  0.00047248457399797254f,0.128747426620186f,    -0.01736930100202211f,
 -0.04408825393106472f,   0.013981027917015516f,  0.008746094047015655f,
 -0.00487035299301066f,  -0.0003917403729959771f, 0.0006754494059985568f,
 -0.00011747678400228192f
};

__device__ float g_lo[(size_t)NM*NH*SW];
__device__ float g_hi[(size_t)NM*NH*SW];
__device__ float g_ll[(size_t)NM*SW*SW];
__device__ float g_lh[(size_t)NM*SW*SW];
__device__ float g_hl[(size_t)NM*SW*SW];
__device__ float g_hh[(size_t)NM*SW*SW];
__device__ float g_thr[NM];

__device__ __forceinline__ int refl(int q, int n) {
  q = (q < 0) ? (-q - 1) : q;
  return (q >= n) ? (2*n - 1 - q) : q;
}
__device__ __forceinline__ float softf(float c, float t) {
  float a = fabsf(c) - t;
  return (a > 0.f) ? copysignf(a, c) : 0.f;
}

// ---- A: row DWT (along W), NHWC input --------------------------------------
__global__ void __launch_bounds__(256) k_fwd_rows(const float* __restrict__ x) {
  __shared__ float s[3*576];
  int h = blockIdx.x, b = blockIdx.y;
  const float4* row4 = (const float4*)(x + (size_t)(b*NH + h)*NW*3);
  for (int i = threadIdx.x; i < 384; i += 256) {
    float4 v = row4[i];
    int lin = 4*i;
    #pragma unroll
    for (int e = 0; e < 4; e++) {
      int l = lin + e, c = l % 3, w = l / 3;
      s[c*576 + w + (w >> 3)] = (&v.x)[e];
    }
  }
  __syncthreads();
  int t = threadIdx.x;
  if (t < 198) {
    int c = t / 66, g = t - 66*c;
    const float* sc = s + c*576;
    float samp[22];
    int q0 = 8*g - 14;
    #pragma unroll
    for (int k = 0; k < 22; k++) { int q = refl(q0 + k, NW); samp[k] = sc[q + (q >> 3)]; }
    float a[4], d[4];
    #pragma unroll
    for (int r = 0; r < 4; r++) {
      float av = 0.f, dv = 0.f;
      #pragma unroll
      for (int i = 0; i < 16; i++) {
        float v = samp[2*r + i];
        av += RL[i] * v;
        dv += ((i & 1) ? -RL[15-i] : RL[15-i]) * v;
      }
      a[r] = av; d[r] = dv;
    }
    size_t base = ((size_t)(b*3 + c)*NH + h)*SW + 4*g;
    *(float4*)(g_lo + base) = make_float4(a[0],a[1],a[2],a[3]);
    *(float4*)(g_hi + base) = make_float4(d[0],d[1],d[2],d[3]);
  }
}

// ---- B: column DWT (along H); outputs [m][w][jh], pads exact zero ----------
__global__ void __launch_bounds__(256) k_fwd_cols() {
  extern __shared__ float s2[]; // [32][513]
  int m = blockIdx.y, w0 = blockIdx.x*32, z = blockIdx.z;
  const float* in = (z ? g_hi : g_lo) + (size_t)m*NH*SW;
  float* outA = (z ? g_hl : g_ll) + (size_t)m*SW*SW;
  float* outD = (z ? g_hh : g_lh) + (size_t)m*SW*SW;
  for (int idx = threadIdx.x; idx < 32*NH; idx += 256) {
    int wl = idx & 31, hh = idx >> 5, w = w0 + wl;
    s2[wl*513 + hh] = (w < NCo) ? in[(size_t)hh*SW + w] : 0.f;
  }
  __syncthreads();
  int lane = threadIdx.x & 31, warp = threadIdx.x >> 5;
  int w = w0 + lane;
  bool wok = (w < SW);
  const float* col = s2 + lane*513;
  for (int g = warp; g < 66; g += 8) {
    int q0 = 8*g - 14;
    float samp[22];
    #pragma unroll
    for (int k = 0; k < 22; k++) { int q = refl(q0 + k, NH); samp[k] = col[q]; }
    float a[4], d[4];
    #pragma unroll
    for (int r = 0; r < 4; r++) {
      float av = 0.f, dv = 0.f;
      #pragma unroll
      for (int i = 0; i < 16; i++) {
        float v = samp[2*r + i];
        av += RL[i] * v;
        dv += ((i & 1) ? -RL[15-i] : RL[15-i]) * v;
      }
      a[r] = av; d[r] = dv;
    }
    if (g == 65) { a[3] = 0.f; d[3] = 0.f; } // jh==263 pad
    if (wok) {
      size_t ob = (size_t)w*SW + 4*g;
      *(float4*)(outA + ob) = make_float4(a[0],a[1],a[2],a[3]);
      *(float4*)(outD + ob) = make_float4(d[0],d[1],d[2],d[3]);
    }
  }
}

// ---- M: exact median via 3-pass radix select (11/11/10 bits) ---------------
__global__ void __launch_bounds__(512) k_median() {
  int m = blockIdx.x;
  __shared__ unsigned hist[2048];
  __shared__ unsigned s_prefix, s_rank;
  const float* bands[3] = { g_lh + (size_t)m*SW*SW, g_hl + (size_t)m*SW*SW,
                            g_hh + (size_t)m*SW*SW };
  if (threadIdx.x == 0) { s_prefix = 0u; s_rank = RANKSEL; }
  const int N4 = SW*SW/4;
  const int shifts[3] = {21, 10, 0};
  const int nbs[3]    = {11, 11, 10};
  for (int pass = 0; pass < 3; pass++) {
    int shift = shifts[pass], nb = nbs[pass];
    unsigned nbins = 1u << nb;
    for (int i = threadIdx.x; i < 2048; i += 512) hist[i] = 0u;
    __syncthreads();
    unsigned prefix = s_prefix;
    for (int band = 0; band < 3; band++) {
      const float4* p = (const float4*)bands[band];
      for (int i = threadIdx.x; i < N4; i += 512) {
        float4 v = p[i];
        #pragma unroll
        for (int e = 0; e < 4; e++) {
          unsigned key = __float_as_uint(fabsf((&v.x)[e]));
          bool ok = (pass == 0) || ((key >> (shift + nb)) == prefix);
          unsigned val = ok ? ((key >> shift) & (nbins - 1u)) : 4095u;
          unsigned mk = __match_any_sync(__activemask(), val);
          if (ok && (int)(threadIdx.x & 31) == (__ffs((int)mk) - 1))
            atomicAdd(&hist[val], (unsigned)__popc(mk));
        }
      }
    }
    __syncthreads();
    if (threadIdx.x == 0) {
      unsigned r = s_rank, cum = 0u, b = 0u;
      for (; b < nbins; b++) { unsigned hb = hist[b]; if (cum + hb > r) break; cum += hb; }
      s_prefix = (prefix << nb) | b;
      s_rank = r - cum;
    }
    __syncthreads();
  }
  if (threadIdx.x == 0) {
    double med = (double)__uint_as_float(s_prefix);
    g_thr[m] = (float)(med / 0.6745 * sqrt(2.0 * log(262144.0)));
  }
}

// ---- C: inverse DWT along H, soft-threshold fused into smem load -----------
__global__ void __launch_bounds__(256) k_inv_cols() {
  extern __shared__ float smc[]; // ca[32*CST] ++ cd[32*CST]
  float* ca = smc; float* cd = smc + 32*CST;
  int m = blockIdx.y, w0 = blockIdx.x*32, z = blockIdx.z;
  const float* A = (z ? g_hl : g_ll) + (size_t)m*SW*SW;
  const float* D = (z ? g_hh : g_lh) + (size_t)m*SW*SW;
  float* out = (z ? g_hi : g_lo) + (size_t)m*NH*SW;
  float thr = g_thr[m];
  for (int idx = threadIdx.x; idx < 32*NCo; idx += 256) {
    int wl = idx / NCo, hh = idx - NCo*wl, w = w0 + wl;
    float va = 0.f, vd = 0.f;
    if (w < NCo) { va = A[(size_t)w*SW + hh]; vd = D[(size_t)w*SW + hh]; }
    if (z) va = softf(va, thr);
    vd = softf(vd, thr);
    ca[wl*CST + hh] = va;
    cd[wl*CST + hh] = vd;
  }
  __syncthreads();
  int lane = threadIdx.x & 31, warp = threadIdx.x >> 5;
  int w = w0 + lane;
  bool wok = (w < NCo);
  const float* cap = ca + lane*CST;
  const float* cdp = cd + lane*CST;
  for (int gc = warp; gc < 64; gc += 8) {
    int p0 = 4*gc;
    float ac[11], dc[11];
    #pragma unroll
    for (int k = 0; k < 11; k++) { ac[k] = cap[p0 + k]; dc[k] = cdp[p0 + k]; }
    #pragma unroll
    for (int r = 0; r < 4; r++) {
      float y0 = 0.f, y1 = 0.f;
      #pragma unroll
      for (int u = 0; u < 8; u++) {
        float va = ac[r + 7 - u], vd = dc[r + 7 - u];
        y0 += va * RL[2*u]     + vd * RL[15 - 2*u];
        y1 += va * RL[2*u + 1] - vd * RL[14 - 2*u];
      }
      if (wok) {
        int i0 = 2*(p0 + r);
        out[(size_t)i0*SW + w]     = y0;
        out[(size_t)(i0+1)*SW + w] = y1;
      }
    }
  }
}

// ---- D: inverse DWT along W + NHWC interleave (staged coalesced store) -----
__global__ void __launch_bounds__(256) k_inv_rows(float* __restrict__ out) {
  __shared__ float ca[3*330], cd[3*330], rowbuf[1536];
  int h = blockIdx.x, b = blockIdx.y;
  for (int c = 0; c < 3; c++) {
    const float* rl = g_lo + ((size_t)(b*3 + c)*NH + h)*SW;
    const float* rh = g_hi + ((size_t)(b*3 + c)*NH + h)*SW;
    for (int wdx = threadIdx.x; wdx < NCo; wdx += 256) {
      int a = wdx + (wdx >> 2);
      ca[c*330 + a] = rl[wdx];
      cd[c*330 + a] = rh[wdx];
    }
  }
  __syncthreads();
  int t = threadIdx.x;
  if (t < 192) {
    int c = t >> 6, gc = t & 63, p0 = 4*gc;
    const float* cap = ca + c*330;
    const float* cdp = cd + c*330;
    float ac[11], dc[11];
    #pragma unroll
    for (int k = 0; k < 11; k++) {
      int a = (p0 + k) + ((p0 + k) >> 2);
      ac[k] = cap[a]; dc[k] = cdp[a];
    }
    #pragma unroll
    for (int r = 0; r < 4; r++) {
      float y0 = 0.f, y1 = 0.f;
      #pragma unroll
      for (int u = 0; u < 8; u++) {
        float va = ac[r + 7 - u], vd = dc[r + 7 - u];
        y0 += va * RL[2*u]     + vd * RL[15 - 2*u];
        y1 += va * RL[2*u + 1] - vd * RL[14 - 2*u];
      }
      int o = 2*(p0 + r);
      rowbuf[o*3 + c]       = y0;
      rowbuf[(o + 1)*3 + c] = y1;
    }
  }
  __syncthreads();
  float4* orow = (float4*)(out + (size_t)(b*NH + h)*NW*3);
  for (int i = threadIdx.x; i < 384; i += 256) orow[i] = ((float4*)rowbuf)[i];
}

extern "C" void kernel_launch(void* const* d_in, const int* in_sizes, int n_in,
                              void* d_out, int out_size) {
  const float* x = (const float*)d_in[0];
  float* out = (float*)d_out;
  cudaFuncSetAttribute(k_fwd_cols, cudaFuncAttributeMaxDynamicSharedMemorySize, 32*513*4);
  cudaFuncSetAttribute(k_inv_cols, cudaFuncAttributeMaxDynamicSharedMemorySize, 2*32*CST*4);
  k_fwd_rows<<<dim3(NH, NB), 256>>>(x);
  k_fwd_cols<<<dim3(9, NM, 2), 256, 32*513*4>>>();
  k_median<<<NM, 512>>>();
  k_inv_cols<<<dim3(9, NM, 2), 256, 2*32*CST*4>>>();
  k_inv_rows<<<dim3(NH, NB), 256>>>(out);
}